// round 10
// baseline (speedup 1.0000x reference)
#include <cuda_runtime.h>

#define BB 4
#define NN 512
#define MM 512
#define DD 128
#define TILE 64

typedef unsigned long long u64;

// ---------------- device scratch (no allocations allowed) ----------------
__device__ float g_z [BB * NN * MM];     // 4 MB z[b][n][m]
__device__ float g_zt[BB * MM * NN];     // 4 MB z^T[b][m][n]
__device__ float g_rmin[BB * NN];
__device__ float g_rinv[BB * NN];
__device__ float g_cmin[BB * MM];
__device__ float g_cinv[BB * MM];
__device__ float g_pnum[BB * NN];
__device__ float g_pden[BB * NN];
__device__ int   g_cnt[BB];              // per-batch last-block counters
__device__ int   g_done;                 // soft grid-barrier counter

// int32-vs-int64 length sniff (jax canonicalization)
__device__ __forceinline__ int load_len(const void* p, int i) {
    const unsigned* u = (const unsigned*)p;
    if (u[1] == 0u) return (int)((const long long*)p)[i];
    return ((const int*)p)[i];
}

// ---------------- packed f32x2 helpers (Blackwell) ----------------
__device__ __forceinline__ u64 pk2(float lo, float hi) {
    u64 r; asm("mov.b64 %0, {%1, %2};" : "=l"(r) : "f"(lo), "f"(hi)); return r;
}
__device__ __forceinline__ u64 add2(u64 a, u64 b) {
    u64 r; asm("add.rn.f32x2 %0, %1, %2;" : "=l"(r) : "l"(a), "l"(b)); return r;
}
__device__ __forceinline__ void upk2(u64 v, float& lo, float& hi) {
    asm("mov.b64 {%0, %1}, %2;" : "=f"(lo), "=f"(hi) : "l"(v));
}

// ---------------- kernel 1: pairwise L1 distance (best R4 shape + z^T) ---
// Grid (8, 8, 4) = 256 blocks; 256 threads; 64x64 tile, 4n x 4m micro,
// m-packed accumulators. Stores BOTH z and z^T from the register tile.
__global__ __launch_bounds__(256) void k_zdiff(
    const float* __restrict__ x, const float* __restrict__ y,
    const void* __restrict__ xlen, const void* __restrict__ ylen) {
    if (blockIdx.x == 0 && blockIdx.y == 0 && blockIdx.z == 0) {
        if (threadIdx.x < BB) g_cnt[threadIdx.x] = 0;
        if (threadIdx.x == BB) g_done = 0;
    }

    int b = blockIdx.z;
    int n0 = blockIdx.y * TILE;
    int m0 = blockIdx.x * TILE;
    int xl = load_len(xlen, b);
    int yl = load_len(ylen, b);
    if (n0 >= xl || m0 >= yl) return;

    __shared__ float xs[64 * 64];   // [d][n]
    __shared__ float ys[64 * 64];   // [d][m], NEGATED y

    int tid = threadIdx.x;
    int ty = tid >> 4;      // 0..15 -> 4 n rows
    int tx = tid & 15;      // 0..15 -> 4 m cols

    const float* xb = x + ((size_t)b * NN + n0) * DD;
    const float* yb = y + ((size_t)b * MM + m0) * DD;

    u64 acc2[4][2];         // [n][m-pair]
#pragma unroll
    for (int i = 0; i < 4; i++) { acc2[i][0] = 0ull; acc2[i][1] = 0ull; }

    const u64 ABSM = 0x7FFFFFFF7FFFFFFFull;

#pragma unroll
    for (int p = 0; p < 2; p++) {
#pragma unroll
        for (int it = 0; it < 4; it++) {
            int idx = tid + 256 * it;
            int n  = idx & 63;
            int dq = idx >> 6;          // 0..15
            const float4 vx = *(const float4*)(xb + (size_t)n * DD + p * 64 + dq * 4);
            const float4 vy = *(const float4*)(yb + (size_t)n * DD + p * 64 + dq * 4);
            xs[(dq * 4 + 0) * 64 + n] = vx.x;
            xs[(dq * 4 + 1) * 64 + n] = vx.y;
            xs[(dq * 4 + 2) * 64 + n] = vx.z;
            xs[(dq * 4 + 3) * 64 + n] = vx.w;
            ys[(dq * 4 + 0) * 64 + n] = -vy.x;
            ys[(dq * 4 + 1) * 64 + n] = -vy.y;
            ys[(dq * 4 + 2) * 64 + n] = -vy.z;
            ys[(dq * 4 + 3) * 64 + n] = -vy.w;
        }
        __syncthreads();

#pragma unroll 8
        for (int d = 0; d < 64; d++) {
            float4 lx = *(const float4*)(xs + d * 64 + ty * 4);
            float4 ln = *(const float4*)(ys + d * 64 + tx * 4);
            u64 ny0 = pk2(ln.x, ln.y);
            u64 ny1 = pk2(ln.z, ln.w);
            float xa[4] = {lx.x, lx.y, lx.z, lx.w};
#pragma unroll
            for (int i = 0; i < 4; i++) {
                u64 xx = pk2(xa[i], xa[i]);
                u64 t0 = add2(xx, ny0) & ABSM;
                u64 t1 = add2(xx, ny1) & ABSM;
                acc2[i][0] = add2(acc2[i][0], t0);
                acc2[i][1] = add2(acc2[i][1], t1);
            }
        }
        __syncthreads();
    }

    // unpack to 4x4 scalar tile
    float af[4][4];
#pragma unroll
    for (int i = 0; i < 4; i++) {
        upk2(acc2[i][0], af[i][0], af[i][1]);
        upk2(acc2[i][1], af[i][2], af[i][3]);
    }

    // z: 4 n-rows x float4
    float* zb = g_z + ((size_t)b * NN + n0 + ty * 4) * MM + m0 + tx * 4;
#pragma unroll
    for (int i = 0; i < 4; i++)
        *(float4*)(zb + (size_t)i * MM) = make_float4(af[i][0], af[i][1], af[i][2], af[i][3]);

    // z^T: 4 m-rows x float4
    float* ztb = g_zt + ((size_t)b * MM + m0 + tx * 4) * NN + n0 + ty * 4;
#pragma unroll
    for (int j = 0; j < 4; j++)
        *(float4*)(ztb + (size_t)j * NN) = make_float4(af[0][j], af[1][j], af[2][j], af[3][j]);
}

// ---------------- kernel 2: fused stats + accum (soft grid barrier) ------
// 512 blocks x 256 thr, launch_bounds(256,4) -> all blocks co-resident
// (592 slots >= 512), so the counter-spin barrier cannot deadlock.
// Phase A: warps 0-3 row-stats on z (rows i*4+w), warps 4-7 col-stats on z^T.
// Barrier (release/acquire). Phase B: 2 warps per z-row (L1-hot from phase A),
// fixed-order combines; last block per batch does the final reduction.
__global__ __launch_bounds__(256, 4) void k_post(
    const void* __restrict__ xlen, const void* __restrict__ ylen,
    float* __restrict__ out) {
    int tid = threadIdx.x;
    int lane = tid & 31;
    int w = tid >> 5;
    int i = blockIdx.x;
    int b = i >> 7;                      // 128 blocks per batch
    int xl = load_len(xlen, b);
    int yl = load_len(ylen, b);

    // ---------------- Phase A: softmax stats ----------------
    {
        int idx = (i & 127) * 4 + (w & 3);   // 0..511 within batch
        const float* src; float* omin; float* oinv;
        int len; bool valid;
        if (w < 4) {
            valid = idx < xl; len = yl;
            src = g_z + ((size_t)b * NN + idx) * MM;
            omin = g_rmin + b * NN + idx;
            oinv = g_rinv + b * NN + idx;
        } else {
            valid = idx < yl; len = xl;
            src = g_zt + ((size_t)b * MM + idx) * NN;
            omin = g_cmin + b * MM + idx;
            oinv = g_cinv + b * MM + idx;
        }
        if (valid) {
            const float4* s4 = (const float4*)src;
            int nv4 = len >> 2;
            int base = len & ~3;
            float zmin = 3.0e38f;
#pragma unroll 4
            for (int k = lane; k < nv4; k += 32) {
                float4 v = s4[k];
                zmin = fminf(zmin, fminf(fminf(v.x, v.y), fminf(v.z, v.w)));
            }
            if (base + lane < len) zmin = fminf(zmin, src[base + lane]);
#pragma unroll
            for (int o = 16; o; o >>= 1) zmin = fminf(zmin, __shfl_xor_sync(0xffffffffu, zmin, o));

            float s = 0.0f;
#pragma unroll 4
            for (int k = lane; k < nv4; k += 32) {
                float4 v = s4[k];
                s += __expf(zmin - v.x) + __expf(zmin - v.y)
                   + __expf(zmin - v.z) + __expf(zmin - v.w);
            }
            if (base + lane < len) s += __expf(zmin - src[base + lane]);
#pragma unroll
            for (int o = 16; o; o >>= 1) s += __shfl_xor_sync(0xffffffffu, s, o);

            if (lane == 0) { *omin = zmin; *oinv = 1.0f / s; }
        }
    }

    // ---------------- soft grid barrier ----------------
    __syncthreads();
    if (tid == 0) {
        __threadfence();                     // release my stats
        atomicAdd(&g_done, 1);
        while (*(volatile int*)&g_done < 512) __nanosleep(64);
    }
    __syncthreads();
    __threadfence();                         // acquire everyone's stats

    // ---------------- Phase B: combine alpha/beta ----------------
    __shared__ float s_pn[4][2];
    __shared__ float s_pd[4][2];
    {
        int rr = (i & 127) * 4 + (w & 3);    // row n within batch (same as A)
        int h  = w >> 2;                      // half index 0/1
        if (rr < xl) {
            const float*  zr  = g_z + ((size_t)b * NN + rr) * MM;
            const float4* z4  = (const float4*)zr;
            const float*  cmn = g_cmin + b * MM;
            const float*  civ = g_cinv + b * MM;
            const float4* cm4 = (const float4*)cmn;
            const float4* ci4 = (const float4*)civ;
            float rmin = g_rmin[b * NN + rr];
            float rinv = g_rinv[b * NN + rr];

            int nv4 = yl >> 2;
            int base = yl & ~3;

            float num = 0.0f, den = 0.0f;
#pragma unroll 2
            for (int k = lane + h * 32; k < nv4; k += 64) {
                float4 z = z4[k];
                float4 cm = cm4[k];
                float4 ci = ci4[k];
                {
                    float beta  = __expf(rmin - z.x) * rinv;
                    float alpha = __expf(cm.x - z.x) * ci.x;
                    float a = alpha + beta - alpha * beta;
                    den += a; num += a * z.x;
                }
                {
                    float beta  = __expf(rmin - z.y) * rinv;
                    float alpha = __expf(cm.y - z.y) * ci.y;
                    float a = alpha + beta - alpha * beta;
                    den += a; num += a * z.y;
                }
                {
                    float beta  = __expf(rmin - z.z) * rinv;
                    float alpha = __expf(cm.z - z.z) * ci.z;
                    float a = alpha + beta - alpha * beta;
                    den += a; num += a * z.z;
                }
                {
                    float beta  = __expf(rmin - z.w) * rinv;
                    float alpha = __expf(cm.w - z.w) * ci.w;
                    float a = alpha + beta - alpha * beta;
                    den += a; num += a * z.w;
                }
            }
            if (h == 0 && base + lane < yl) {
                int m = base + lane;
                float z = zr[m];
                float beta  = __expf(rmin - z) * rinv;
                float alpha = __expf(cmn[m] - z) * civ[m];
                float a = alpha + beta - alpha * beta;
                den += a; num += a * z;
            }
#pragma unroll
            for (int o = 16; o; o >>= 1) {
                num += __shfl_xor_sync(0xffffffffu, num, o);
                den += __shfl_xor_sync(0xffffffffu, den, o);
            }
            if (lane == 0) { s_pn[w & 3][h] = num; s_pd[w & 3][h] = den; }
        }
    }
    __syncthreads();
    if (w < 4 && lane == 0) {
        int rr = (i & 127) * 4 + w;
        if (rr < xl) {
            g_pnum[b * NN + rr] = s_pn[w][0] + s_pn[w][1];
            g_pden[b * NN + rr] = s_pd[w][0] + s_pd[w][1];
        }
    }

    // ---------------- last-block final reduction ----------------
    __shared__ int s_last;
    __syncthreads();
    if (tid == 0) {
        __threadfence();
        int old = atomicAdd(&g_cnt[b], 1);
        s_last = (old == 127);
    }
    __syncthreads();
    if (!s_last) return;
    __threadfence();

    float num = 0.0f, den = 0.0f;
    for (int k = tid; k < xl; k += 256) {
        num += g_pnum[b * NN + k];
        den += g_pden[b * NN + k];
    }
    __shared__ float sn[256];
    __shared__ float sd[256];
    sn[tid] = num;
    sd[tid] = den;
    __syncthreads();
    for (int s2 = 128; s2; s2 >>= 1) {
        if (tid < s2) {
            sn[tid] += sn[tid + s2];
            sd[tid] += sd[tid + s2];
        }
        __syncthreads();
    }
    if (tid == 0) out[b] = -sn[0] / sd[0];
}

// ---------------- launch ----------------
extern "C" void kernel_launch(void* const* d_in, const int* in_sizes, int n_in,
                              void* d_out, int out_size) {
    const float* x = (const float*)d_in[0];
    const float* y = (const float*)d_in[1];
    const void* xl = d_in[2];
    const void* yl = d_in[3];
    float* out = (float*)d_out;

    dim3 g1(MM / TILE, NN / TILE, BB);      // (8, 8, 4) = 256 blocks
    k_zdiff<<<g1, 256>>>(x, y, xl, yl);
    k_post<<<512, 256>>>(xl, yl, out);
}